// round 11
// baseline (speedup 1.0000x reference)
#include <cuda_runtime.h>
#include <cuda_fp16.h>
#include <cstdint>
#include <cstddef>

#define Bx 4
#define Vx 64
#define Ex 1024
#define Lx 1024
#define NR (Bx * Vx * Lx)          // 262144 rows

#define F32STR 36                  // gemm1 fp32 A stage row stride (floats)
#define ASTRh  40                  // gemm1 fp16 A row stride (halfs)
#define BSTRh  264                 // gemm1 B row stride (halfs)
#define HSTR   264                 // attn Xh/Zh row stride (halfs)
#define BSS    36                  // attn score row stride (floats)

__device__ __align__(16) __half g_Mh[256 * 256];   // Mh[n][k] = (Wq^T Wk)[k][n]
__device__ __align__(16) float  g_r[256];          // r[n] = sum_c bq[c]*Wk[c][n]
__device__ __align__(16) float  g_Mp[4 * 256 * 256];  // precompute partials [dq][n][k]
__device__ __align__(16) float  g_rp[4 * 256];        // r partials [dq][n]
__device__ __align__(16) __half g_Xh[(size_t)NR * 256];   // fp16 hidden_states
__device__ __align__(16) __half g_Z [(size_t)NR * 256];   // Z = X @ M + r  (r folded)

__device__ __forceinline__ unsigned packh2(float a, float b) {
    __half2 h = __floats2half2_rn(a, b);
    return *reinterpret_cast<unsigned*>(&h);
}

__device__ __forceinline__ void mma_f16(float (&d)[4], const unsigned (&a)[4],
                                        unsigned b0, unsigned b1) {
    asm volatile("mma.sync.aligned.m16n8k16.row.col.f32.f16.f16.f32 "
                 "{%0,%1,%2,%3}, {%4,%5,%6,%7}, {%8,%9}, {%0,%1,%2,%3};"
                 : "+f"(d[0]), "+f"(d[1]), "+f"(d[2]), "+f"(d[3])
                 : "r"(a[0]), "r"(a[1]), "r"(a[2]), "r"(a[3]), "r"(b0), "r"(b1));
}

__device__ __forceinline__ void cp16(void* smem_dst, const void* gsrc) {
    unsigned d = (unsigned)__cvta_generic_to_shared(smem_dst);
    asm volatile("cp.async.ca.shared.global [%0], [%1], 16;" :: "r"(d), "l"(gsrc));
}

__device__ __forceinline__ void ldsm_x4(unsigned &r0, unsigned &r1, unsigned &r2,
                                        unsigned &r3, const void* p) {
    unsigned a = (unsigned)__cvta_generic_to_shared(p);
    asm volatile("ldmatrix.sync.aligned.m8n8.x4.shared.b16 {%0,%1,%2,%3}, [%4];"
                 : "=r"(r0), "=r"(r1), "=r"(r2), "=r"(r3) : "r"(a));
}

// ---------------- K0a: partial M over d-quarters (4x parallelism) ----------------
__global__ void pre_a(const float* __restrict__ Wq, const float* __restrict__ bq,
                      const float* __restrict__ Wk)
{
    __shared__ float sWk[64];
    __shared__ float red[2];
    const int n = blockIdx.x, dq = blockIdx.y, j = threadIdx.x;
    if (j < 64) sWk[j] = Wk[(dq * 64 + j) * 256 + n];
    __syncthreads();
    float acc = 0.f;
    const float* wq = Wq + (dq * 64) * 256 + j;
    #pragma unroll 8
    for (int dd = 0; dd < 64; dd++)
        acc = fmaf(wq[dd * 256], sWk[dd], acc);
    g_Mp[(dq * 256 + n) * 256 + j] = acc;

    if (j < 64) {
        float pr = bq[dq * 64 + j] * sWk[j];
        #pragma unroll
        for (int off = 16; off > 0; off >>= 1)
            pr += __shfl_xor_sync(~0u, pr, off);
        if ((j & 31) == 0) red[j >> 5] = pr;
    }
    __syncthreads();
    if (j == 0) g_rp[dq * 256 + n] = red[0] + red[1];
}

// ---------------- K0b: sum partials -> fp16 M, r ----------------
__global__ void pre_b()
{
    const int n = blockIdx.x, j = threadIdx.x;
    float s = g_Mp[n * 256 + j] + g_Mp[(256 + n) * 256 + j]
            + g_Mp[(512 + n) * 256 + j] + g_Mp[(768 + n) * 256 + j];
    g_Mh[n * 256 + j] = __float2half_rn(s);
    if (j == 0)
        g_r[n] = g_rp[n] + g_rp[256 + n] + g_rp[512 + n] + g_rp[768 + n];
}

// ---------------- K1: fused convert + GEMM  Z = Xh @ Mh^T + r ----------------
// grid 2048: 128-row tile, FULL n=256 (B resident). 512 threads = 4m x 4n warps (m32 x n64).
__global__ __launch_bounds__(512, 1) void gemm1_kernel(const float* __restrict__ hs)
{
    extern __shared__ char smraw1[];
    float*  F   = (float*)smraw1;                        // 128 x F32STR fp32 stage
    __half* Ah  = (__half*)(F + 128 * F32STR);           // 2 x 128 x ASTRh
    __half* Bs  = Ah + 2 * 128 * ASTRh;                  // 256 x BSTRh
    float*  Sr  = (float*)(Bs + 256 * BSTRh);            // 256
    __half* Zst = Bs;                                    // epilogue overlay (B dead)

    const int t = threadIdx.x, w = t >> 5, j = t & 31;
    const int r0 = blockIdx.x * 128;
    const int rA = j >> 2, cA = j & 3;
    const int mb = (w & 3) * 32, nb = (w >> 2) * 64;

    // stage B (256 n-rows x 256 k halfs) + Sr
    #pragma unroll
    for (int i = 0; i < 16; i++) {
        int idx = i * 512 + t, nl = idx >> 5, q = idx & 31;
        cp16(Bs + nl * BSTRh + q * 8, g_Mh + nl * 256 + q * 8);
    }
    if (t < 64) ((float4*)Sr)[t] = __ldg((const float4*)(g_r) + t);
    // stage fp32 A chunk 0
    #pragma unroll
    for (int i = 0; i < 2; i++) {
        int idx = i * 512 + t, row = idx >> 3, q = idx & 7;
        cp16(F + row * F32STR + q * 4, hs + (size_t)(r0 + row) * 256 + q * 4);
    }
    asm volatile("cp.async.commit_group;" ::: "memory");

    float acc[2][8][4];
    #pragma unroll
    for (int a = 0; a < 2; a++)
        #pragma unroll
        for (int c = 0; c < 8; c++)
            #pragma unroll
            for (int q = 0; q < 4; q++) acc[a][c][q] = 0.f;

    const int cvrow = t >> 2, cvq = t & 3;       // convert: 4 threads per row, 8 floats each

    #pragma unroll 1
    for (int kt = 0; kt < 8; kt++) {
        asm volatile("cp.async.wait_group 0;" ::: "memory");
        __syncthreads();
        // convert fp32 chunk -> fp16 Ah[kt&1], and write g_Xh
        __half* A = Ah + (kt & 1) * 128 * ASTRh;
        {
            const float* fp = F + cvrow * F32STR + cvq * 8;
            float4 f0 = *(const float4*)(fp);
            float4 f1 = *(const float4*)(fp + 4);
            uint4 o;
            o.x = packh2(f0.x, f0.y); o.y = packh2(f0.z, f0.w);
            o.z = packh2(f1.x, f1.y); o.w = packh2(f1.z, f1.w);
            *(uint4*)(A + cvrow * ASTRh + cvq * 8) = o;
            *(uint4*)(g_Xh + (size_t)(r0 + cvrow) * 256 + kt * 32 + cvq * 8) = o;
        }
        __syncthreads();
        if (kt < 7) {                             // prefetch next fp32 chunk
            #pragma unroll
            for (int i = 0; i < 2; i++) {
                int idx = i * 512 + t, row = idx >> 3, q = idx & 7;
                cp16(F + row * F32STR + q * 4,
                     hs + (size_t)(r0 + row) * 256 + (kt + 1) * 32 + q * 4);
            }
            asm volatile("cp.async.commit_group;" ::: "memory");
        }

        #pragma unroll
        for (int ks = 0; ks < 2; ks++) {
            const int kcB = kt * 32 + ks * 16;
            unsigned a[2][4];
            #pragma unroll
            for (int mt = 0; mt < 2; mt++) {
                int arow = mb + mt * 16 + (j & 7) + ((j >> 3) & 1) * 8;
                ldsm_x4(a[mt][0], a[mt][1], a[mt][2], a[mt][3],
                        A + arow * ASTRh + ks * 16 + (j >> 4) * 8);
            }
            #pragma unroll
            for (int p = 0; p < 4; p++) {
                unsigned b0, b1, b2, b3;
                int brow = nb + p * 16 + (j >> 4) * 8 + (j & 7);
                ldsm_x4(b0, b1, b2, b3,
                        Bs + brow * BSTRh + kcB + ((j >> 3) & 1) * 8);
                mma_f16(acc[0][2 * p],     a[0], b0, b1);
                mma_f16(acc[1][2 * p],     a[1], b0, b1);
                mma_f16(acc[0][2 * p + 1], a[0], b2, b3);
                mma_f16(acc[1][2 * p + 1], a[1], b2, b3);
            }
        }
    }
    __syncthreads();

    // epilogue: add r, pack fp16 into overlay, coalesced STG.128
    #pragma unroll
    for (int mt = 0; mt < 2; mt++)
        #pragma unroll
        for (int nt = 0; nt < 8; nt++) {
            int row = mb + mt * 16 + rA;
            int col = nb + nt * 8 + 2 * cA;
            float rc0 = Sr[col], rc1 = Sr[col + 1];
            *(unsigned*)(Zst + row * BSTRh + col) =
                packh2(acc[mt][nt][0] + rc0, acc[mt][nt][1] + rc1);
            *(unsigned*)(Zst + (row + 8) * BSTRh + col) =
                packh2(acc[mt][nt][2] + rc0, acc[mt][nt][3] + rc1);
        }
    __syncthreads();
    #pragma unroll
    for (int i = 0; i < 8; i++) {
        int idx = i * 512 + t, row = idx >> 5, q = idx & 31;
        *(uint4*)(g_Z + (size_t)(r0 + row) * 256 + q * 8) =
            *(const uint4*)(Zst + row * BSTRh + q * 8);
    }
}

// ---------------- K2: per (b,l): banded S = (Z+r).X^T, softmax, outputs ----------------
__global__ __launch_bounds__(256, 2)
void attn_kernel(const int*   __restrict__ edge_index,
                 const float* __restrict__ edge_weight,
                 const float* __restrict__ attn_skip_p,
                 float* __restrict__ out)
{
    extern __shared__ char smraw[];
    __half* Xh = (__half*)smraw;                       // 64 x HSTR
    __half* Zh = Xh + 64 * HSTR;                       // 64 x HSTR
    float*  Ss = (float*)(Zh + 64 * HSTR);             // 2 x 64 x BSS
    int*    Sd = (int*)(Ss + 2 * 64 * BSS);            // 1024
    float*  Sew = (float*)(Sd + 1024);                 // 1024

    const int bx = blockIdx.x;
    const int b = bx >> 10, l = bx & 1023;
    const int t = threadIdx.x, w = t >> 5, j = t & 31;
    const int rA = j >> 2, cA = j & 3;

    // stage Xh, Zh slices via cp.async
    #pragma unroll
    for (int i = 0; i < 8; i++) {
        int idx = i * 256 + t, v = idx >> 5, q = idx & 31;
        size_t rowoff = ((size_t)(b * Vx + v) * Lx + l) * 256;
        cp16(Xh + v * HSTR + q * 8, g_Xh + rowoff + q * 8);
        cp16(Zh + v * HSTR + q * 8, g_Z  + rowoff + q * 8);
    }
    asm volatile("cp.async.commit_group;" ::: "memory");

    // ei output fill (overlaps the cp.async)
    {
        const int base = bx * 2048;
        #pragma unroll
        for (int r = 0; r < 8; r++) {
            int idx = base + r * 256 + t;
            out[idx] = (float)edge_index[idx >> 10];
        }
    }
    // dst + edge weights
    {
        const int*   dsts = edge_index + Bx * Ex + b * Ex;
        const float* ews  = edge_weight + b * Ex;
        #pragma unroll
        for (int i = 0; i < 4; i++) {
            Sd[i * 256 + t]  = dsts[i * 256 + t];
            Sew[i * 256 + t] = ews[i * 256 + t];
        }
    }
    asm volatile("cp.async.wait_group 0;" ::: "memory");
    __syncthreads();

    // banded GEMM: S[64][32] = Zh @ Xh[band]^T
    {
        float sacc[4][4];
        #pragma unroll
        for (int c = 0; c < 4; c++)
            #pragma unroll
            for (int q = 0; q < 4; q++) sacc[c][q] = 0.f;

        const int m0 = (w & 3) * 16;
        const int kh = w >> 2;

        #pragma unroll
        for (int ks = 0; ks < 8; ks++) {
            const int kc = kh * 128 + ks * 16;
            unsigned a[4];
            {
                int arow = m0 + (j & 7) + ((j >> 3) & 1) * 8;
                ldsm_x4(a[0], a[1], a[2], a[3],
                        Zh + arow * HSTR + kc + (j >> 4) * 8);
            }
            #pragma unroll
            for (int p = 0; p < 2; p++) {
                unsigned b0, b1, b2, b3;
                int nrow = (m0 + 1 + (2 * p + (j >> 4)) * 8 + (j & 7)) & 63;
                ldsm_x4(b0, b1, b2, b3,
                        Xh + nrow * HSTR + kc + ((j >> 3) & 1) * 8);
                mma_f16(sacc[2 * p],     a, b0, b1);
                mma_f16(sacc[2 * p + 1], a, b2, b3);
            }
        }

        float* SsH = Ss + kh * 64 * BSS;
        #pragma unroll
        for (int nt = 0; nt < 4; nt++) {
            int row = m0 + rA;
            int col = nt * 8 + 2 * cA;
            *(float2*)(SsH + row * BSS + col)       = make_float2(sacc[nt][0], sacc[nt][1]);
            *(float2*)(SsH + (row + 8) * BSS + col) = make_float2(sacc[nt][2], sacc[nt][3]);
        }
    }
    __syncthreads();

    // softmax over each src's 16 neighbors; 16-lane group per src
    const float skip = attn_skip_p[0];
    float* outEw = out + (size_t)2 * Bx * Ex * Lx;
    const int g  = j >> 4;
    const int jj = j & 15;

    #pragma unroll
    for (int it = 0; it < 4; it++) {
        const int v  = it * 16 + w * 2 + g;
        const int dst = Sd[v * 16 + jj];
        const int col = (dst - (v & ~15) - 1) & 63;        // in [0,32)
        float sc = (Ss[v * BSS + col] + Ss[64 * BSS + v * BSS + col]) * 0.0625f;
        float m = sc;
        #pragma unroll
        for (int off = 8; off > 0; off >>= 1) m = fmaxf(m, __shfl_xor_sync(~0u, m, off));
        float e = __expf(sc - m);
        float Zt = e;
        #pragma unroll
        for (int off = 8; off > 0; off >>= 1) Zt += __shfl_xor_sync(~0u, Zt, off);
        const int ge = b * Ex + v * 16 + jj;
        outEw[(size_t)ge * Lx + l] = skip * Sew[v * 16 + jj] + (1.0f - skip) * e / Zt;
    }
}

extern "C" void kernel_launch(void* const* d_in, const int* in_sizes, int n_in,
                              void* d_out, int out_size)
{
    const float* hs = (const float*)d_in[0];
    const int*   ei = (const int*)  d_in[1];
    const float* ew = (const float*)d_in[2];
    const float* Wq = (const float*)d_in[3];
    const float* bq = (const float*)d_in[4];
    const float* Wk = (const float*)d_in[5];
    const float* bk = (const float*)d_in[6];
    const float* sk = (const float*)d_in[7];
    float* out = (float*)d_out;
    (void)bk;

    pre_a<<<dim3(256, 4), 256>>>(Wq, bq, Wk);
    pre_b<<<256, 256>>>();

    const int smem1 = 128 * F32STR * 4 + 2 * 128 * ASTRh * 2 + 256 * BSTRh * 2 + 256 * 4;
    cudaFuncSetAttribute(gemm1_kernel, cudaFuncAttributeMaxDynamicSharedMemorySize, smem1);
    gemm1_kernel<<<2048, 512, smem1>>>(hs);

    const int smem2 = 64 * HSTR * 2 * 2 + 2 * 64 * BSS * 4 + 1024 * 4 * 2;
    cudaFuncSetAttribute(attn_kernel, cudaFuncAttributeMaxDynamicSharedMemorySize, smem2);
    attn_kernel<<<Bx * Lx, 256, smem2>>>(ei, ew, sk, out);
}

// round 12
// speedup vs baseline: 1.1677x; 1.1677x over previous
#include <cuda_runtime.h>
#include <cuda_fp16.h>
#include <cstdint>
#include <cstddef>

#define Bx 4
#define Vx 64
#define Ex 1024
#define Lx 1024
#define NR (Bx * Vx * Lx)          // 262144 rows

#define F32STR 36                  // gemm1 fp32 A stage row stride (floats)
#define ASTRh  40                  // gemm1 fp16 A row stride (halfs)
#define BSTRh  264                 // gemm1 B row stride (halfs)
#define HSTR   264                 // attn Xh/Zh row stride (halfs)
#define BSS    36                  // attn score row stride (floats)

__device__ __align__(16) __half g_Mh[256 * 256];      // Mh[n][k] = (Wq^T Wk)[k][n]
__device__ __align__(16) float  g_r[256];             // r[n] = sum_c bq[c]*Wk[c][n]
__device__ __align__(16) float  g_Mp[4 * 256 * 256];  // precompute partials [dq][n][k]
__device__ __align__(16) float  g_rp[4 * 256];        // r partials [dq][n]
__device__ __align__(16) __half g_Xh[(size_t)NR * 256];   // fp16 hidden_states
__device__ __align__(16) __half g_Z [(size_t)NR * 256];   // Z = X @ M + r (r folded)
__device__ __align__(16) float  g_ewS[(size_t)Bx * Lx * Ex]; // ew, l-major staging

__device__ __forceinline__ unsigned packh2(float a, float b) {
    __half2 h = __floats2half2_rn(a, b);
    return *reinterpret_cast<unsigned*>(&h);
}

__device__ __forceinline__ void mma_f16(float (&d)[4], const unsigned (&a)[4],
                                        unsigned b0, unsigned b1) {
    asm volatile("mma.sync.aligned.m16n8k16.row.col.f32.f16.f16.f32 "
                 "{%0,%1,%2,%3}, {%4,%5,%6,%7}, {%8,%9}, {%0,%1,%2,%3};"
                 : "+f"(d[0]), "+f"(d[1]), "+f"(d[2]), "+f"(d[3])
                 : "r"(a[0]), "r"(a[1]), "r"(a[2]), "r"(a[3]), "r"(b0), "r"(b1));
}

__device__ __forceinline__ void cp16(void* smem_dst, const void* gsrc) {
    unsigned d = (unsigned)__cvta_generic_to_shared(smem_dst);
    asm volatile("cp.async.ca.shared.global [%0], [%1], 16;" :: "r"(d), "l"(gsrc));
}

__device__ __forceinline__ void ldsm_x4(unsigned &r0, unsigned &r1, unsigned &r2,
                                        unsigned &r3, const void* p) {
    unsigned a = (unsigned)__cvta_generic_to_shared(p);
    asm volatile("ldmatrix.sync.aligned.m8n8.x4.shared.b16 {%0,%1,%2,%3}, [%4];"
                 : "=r"(r0), "=r"(r1), "=r"(r2), "=r"(r3) : "r"(a));
}

__device__ __forceinline__ uint32_t smem_u32(const void* p) {
    return (uint32_t)__cvta_generic_to_shared(p);
}
__device__ __forceinline__ void mbar_init(uint32_t a, unsigned cnt) {
    asm volatile("mbarrier.init.shared.b64 [%0], %1;" :: "r"(a), "r"(cnt) : "memory");
}
__device__ __forceinline__ void mbar_expect_tx(uint32_t a, unsigned bytes) {
    asm volatile("mbarrier.arrive.expect_tx.shared.b64 _, [%0], %1;"
                 :: "r"(a), "r"(bytes) : "memory");
}
__device__ __forceinline__ void fence_proxy_async_sc() {
    asm volatile("fence.proxy.async.shared::cta;" ::: "memory");
}
__device__ __forceinline__ void bulk_g2s(uint32_t dst, const void* src,
                                         unsigned bytes, uint32_t mbar) {
    asm volatile("cp.async.bulk.shared::cta.global.mbarrier::complete_tx::bytes "
                 "[%0], [%1], %2, [%3];"
                 :: "r"(dst), "l"(src), "r"(bytes), "r"(mbar) : "memory");
}
__device__ __forceinline__ void mbar_wait(uint32_t a, unsigned parity) {
    asm volatile(
        "{\n\t.reg .pred P;\n\t"
        "WAITL_%=:\n\t"
        "mbarrier.try_wait.parity.acquire.cta.shared::cta.b64 P, [%0], %1, 0x989680;\n\t"
        "@P bra.uni WAITD_%=;\n\t"
        "bra.uni WAITL_%=;\n\t"
        "WAITD_%=:\n\t}"
        :: "r"(a), "r"(parity) : "memory");
}

// ---------------- K0a: partial M over d-quarters ----------------
__global__ void pre_a(const float* __restrict__ Wq, const float* __restrict__ bq,
                      const float* __restrict__ Wk)
{
    __shared__ float sWk[64];
    __shared__ float red[2];
    const int n = blockIdx.x, dq = blockIdx.y, j = threadIdx.x;
    if (j < 64) sWk[j] = Wk[(dq * 64 + j) * 256 + n];
    __syncthreads();
    float acc = 0.f;
    const float* wq = Wq + (dq * 64) * 256 + j;
    #pragma unroll 8
    for (int dd = 0; dd < 64; dd++)
        acc = fmaf(wq[dd * 256], sWk[dd], acc);
    g_Mp[(dq * 256 + n) * 256 + j] = acc;

    if (j < 64) {
        float pr = bq[dq * 64 + j] * sWk[j];
        #pragma unroll
        for (int off = 16; off > 0; off >>= 1)
            pr += __shfl_xor_sync(~0u, pr, off);
        if ((j & 31) == 0) red[j >> 5] = pr;
    }
    __syncthreads();
    if (j == 0) g_rp[dq * 256 + n] = red[0] + red[1];
}

// ---------------- K0b: sum partials -> fp16 M, r ----------------
__global__ void pre_b()
{
    const int n = blockIdx.x, j = threadIdx.x;
    float s = g_Mp[n * 256 + j] + g_Mp[(256 + n) * 256 + j]
            + g_Mp[(512 + n) * 256 + j] + g_Mp[(768 + n) * 256 + j];
    g_Mh[n * 256 + j] = __float2half_rn(s);
    if (j == 0)
        g_r[n] = g_rp[n] + g_rp[256 + n] + g_rp[512 + n] + g_rp[768 + n];
}

// ---------------- K1: fused convert + GEMM  Z = Xh @ Mh^T + r ----------------
// grid (2048, 2): 128-row tile x 128-n half. 256 threads = 4m x 2n warps.
__global__ __launch_bounds__(256, 2) void gemm1_kernel(const float* __restrict__ hs)
{
    extern __shared__ char smraw1[];
    float*  F   = (float*)smraw1;                        // 128 x F32STR
    __half* Ah  = (__half*)(F + 128 * F32STR);           // 2 x 128 x ASTRh
    __half* Bs  = Ah + 2 * 128 * ASTRh;                  // 128 x BSTRh
    float*  Sr  = (float*)(Bs + 128 * BSTRh);            // 128
    unsigned long long* mb = (unsigned long long*)(Sr + 128);
    __half* Zst = Bs;                                    // epilogue overlay

    const int t = threadIdx.x, w = t >> 5, j = t & 31;
    const int r0 = blockIdx.x * 128;
    const int n0 = blockIdx.y * 128;
    const int rA = j >> 2, cA = j & 3;
    const int mb_ = (w & 3) * 32, nb = (w >> 2) * 64;
    const uint32_t mba = smem_u32(mb);

    if (t == 0) {
        mbar_init(mba, 1);
        fence_proxy_async_sc();
        mbar_expect_tx(mba, 128 * 512);
    }
    __syncthreads();
    // stage B via bulk copies (128 rows x 512B)
    if (t < 128)
        bulk_g2s(smem_u32(Bs + t * BSTRh), g_Mh + (n0 + t) * 256, 512, mba);
    if (t < 32) ((float4*)Sr)[t] = __ldg((const float4*)(g_r + n0) + t);
    // stage fp32 A chunk 0
    #pragma unroll
    for (int i = 0; i < 4; i++) {
        int idx = i * 256 + t, row = idx >> 3, q = idx & 7;
        cp16(F + row * F32STR + q * 4, hs + (size_t)(r0 + row) * 256 + q * 4);
    }
    asm volatile("cp.async.commit_group;" ::: "memory");

    float acc[2][8][4];
    #pragma unroll
    for (int a = 0; a < 2; a++)
        #pragma unroll
        for (int c = 0; c < 8; c++)
            #pragma unroll
            for (int q = 0; q < 4; q++) acc[a][c][q] = 0.f;

    const int cvrow = t >> 1, cvh = t & 1;

    mbar_wait(mba, 0);           // B resident

    #pragma unroll 1
    for (int kt = 0; kt < 8; kt++) {
        asm volatile("cp.async.wait_group 0;" ::: "memory");
        __syncthreads();
        // convert fp32 chunk -> fp16 Ah[kt&1]; write g_Xh (n-half 0 only)
        __half* A = Ah + (kt & 1) * 128 * ASTRh;
        {
            const float* fp = F + cvrow * F32STR + cvh * 16;
            float4 f0 = *(const float4*)(fp);
            float4 f1 = *(const float4*)(fp + 4);
            float4 f2 = *(const float4*)(fp + 8);
            float4 f3 = *(const float4*)(fp + 12);
            uint4 o0, o1;
            o0.x = packh2(f0.x, f0.y); o0.y = packh2(f0.z, f0.w);
            o0.z = packh2(f1.x, f1.y); o0.w = packh2(f1.z, f1.w);
            o1.x = packh2(f2.x, f2.y); o1.y = packh2(f2.z, f2.w);
            o1.z = packh2(f3.x, f3.y); o1.w = packh2(f3.z, f3.w);
            __half* ap = A + cvrow * ASTRh + cvh * 16;
            *(uint4*)(ap) = o0;
            *(uint4*)(ap + 8) = o1;
            if (blockIdx.y == 0) {
                __half* gx = g_Xh + (size_t)(r0 + cvrow) * 256 + kt * 32 + cvh * 16;
                *(uint4*)(gx) = o0;
                *(uint4*)(gx + 8) = o1;
            }
        }
        __syncthreads();
        if (kt < 7) {
            #pragma unroll
            for (int i = 0; i < 4; i++) {
                int idx = i * 256 + t, row = idx >> 3, q = idx & 7;
                cp16(F + row * F32STR + q * 4,
                     hs + (size_t)(r0 + row) * 256 + (kt + 1) * 32 + q * 4);
            }
            asm volatile("cp.async.commit_group;" ::: "memory");
        }

        #pragma unroll
        for (int ks = 0; ks < 2; ks++) {
            const int kcB = kt * 32 + ks * 16;
            unsigned a[2][4];
            #pragma unroll
            for (int mt = 0; mt < 2; mt++) {
                int arow = mb_ + mt * 16 + (j & 7) + ((j >> 3) & 1) * 8;
                ldsm_x4(a[mt][0], a[mt][1], a[mt][2], a[mt][3],
                        A + arow * ASTRh + ks * 16 + (j >> 4) * 8);
            }
            #pragma unroll
            for (int p = 0; p < 4; p++) {
                unsigned b0, b1, b2, b3;
                int brow = nb + p * 16 + (j >> 4) * 8 + (j & 7);
                ldsm_x4(b0, b1, b2, b3,
                        Bs + brow * BSTRh + kcB + ((j >> 3) & 1) * 8);
                mma_f16(acc[0][2 * p],     a[0], b0, b1);
                mma_f16(acc[1][2 * p],     a[1], b0, b1);
                mma_f16(acc[0][2 * p + 1], a[0], b2, b3);
                mma_f16(acc[1][2 * p + 1], a[1], b2, b3);
            }
        }
    }
    __syncthreads();

    // epilogue: add r, pack fp16 into overlay, coalesced STG.128
    #pragma unroll
    for (int mt = 0; mt < 2; mt++)
        #pragma unroll
        for (int nt = 0; nt < 8; nt++) {
            int row = mb_ + mt * 16 + rA;
            int col = nb + nt * 8 + 2 * cA;
            float rc0 = Sr[col], rc1 = Sr[col + 1];
            *(unsigned*)(Zst + row * BSTRh + col) =
                packh2(acc[mt][nt][0] + rc0, acc[mt][nt][1] + rc1);
            *(unsigned*)(Zst + (row + 8) * BSTRh + col) =
                packh2(acc[mt][nt][2] + rc0, acc[mt][nt][3] + rc1);
        }
    __syncthreads();
    #pragma unroll
    for (int i = 0; i < 4; i++) {
        int idx = i * 256 + t, row = idx >> 3, q = idx & 7;
        *(uint4*)(g_Z + (size_t)(r0 + row) * 256 + n0 + q * 16) =
            *(const uint4*)(Zst + row * BSTRh + q * 16);
        *(uint4*)(g_Z + (size_t)(r0 + row) * 256 + n0 + q * 16 + 8) =
            *(const uint4*)(Zst + row * BSTRh + q * 16 + 8);
    }
}

// ---------------- K2: per (b,l): banded S = (Z+r).X^T, softmax ----------------
__global__ __launch_bounds__(256, 2)
void attn_kernel(const int*   __restrict__ edge_index,
                 const float* __restrict__ edge_weight,
                 const float* __restrict__ attn_skip_p,
                 float* __restrict__ out)
{
    extern __shared__ char smraw[];
    __half* Xh = (__half*)smraw;                       // 64 x HSTR
    __half* Zh = Xh + 64 * HSTR;                       // 64 x HSTR
    float*  Ss = (float*)(Zh + 64 * HSTR);             // 2 x 64 x BSS
    int*    Sd = (int*)(Ss + 2 * 64 * BSS);            // 1024
    float*  Sew = (float*)(Sd + 1024);                 // 1024
    unsigned long long* mb = (unsigned long long*)(Sew + 1024);

    const int bx = blockIdx.x;
    const int b = bx >> 10, l = bx & 1023;
    const int t = threadIdx.x, w = t >> 5, j = t & 31;
    const int rA = j >> 2, cA = j & 3;
    const uint32_t mba = smem_u32(mb);

    if (t == 0) {
        mbar_init(mba, 1);
        fence_proxy_async_sc();
        mbar_expect_tx(mba, 2 * 64 * 512);
    }
    __syncthreads();
    // stage Xh + Zh: 128 bulk copies of 512B
    if (t < 128) {
        int v = t & 63;
        size_t rowoff = ((size_t)(b * Vx + v) * Lx + l) * 256;
        if (t < 64) bulk_g2s(smem_u32(Xh + v * HSTR), g_Xh + rowoff, 512, mba);
        else        bulk_g2s(smem_u32(Zh + v * HSTR), g_Z  + rowoff, 512, mba);
    }

    // ei output fill (overlaps bulk)
    {
        const int base = bx * 2048;
        #pragma unroll
        for (int r = 0; r < 8; r++) {
            int idx = base + r * 256 + t;
            out[idx] = (float)edge_index[idx >> 10];
        }
    }
    // dst + edge weights
    {
        const int*   dsts = edge_index + Bx * Ex + b * Ex;
        const float* ews  = edge_weight + b * Ex;
        #pragma unroll
        for (int i = 0; i < 4; i++) {
            Sd[i * 256 + t]  = dsts[i * 256 + t];
            Sew[i * 256 + t] = ews[i * 256 + t];
        }
    }
    mbar_wait(mba, 0);
    __syncthreads();

    // banded GEMM: S[64][32] = Zh @ Xh[band]^T
    {
        float sacc[4][4];
        #pragma unroll
        for (int c = 0; c < 4; c++)
            #pragma unroll
            for (int q = 0; q < 4; q++) sacc[c][q] = 0.f;

        const int m0 = (w & 3) * 16;
        const int kh = w >> 2;

        #pragma unroll
        for (int ks = 0; ks < 8; ks++) {
            const int kc = kh * 128 + ks * 16;
            unsigned a[4];
            {
                int arow = m0 + (j & 7) + ((j >> 3) & 1) * 8;
                ldsm_x4(a[0], a[1], a[2], a[3],
                        Zh + arow * HSTR + kc + (j >> 4) * 8);
            }
            #pragma unroll
            for (int p = 0; p < 2; p++) {
                unsigned b0, b1, b2, b3;
                int nrow = (m0 + 1 + (2 * p + (j >> 4)) * 8 + (j & 7)) & 63;
                ldsm_x4(b0, b1, b2, b3,
                        Xh + nrow * HSTR + kc + ((j >> 3) & 1) * 8);
                mma_f16(sacc[2 * p],     a, b0, b1);
                mma_f16(sacc[2 * p + 1], a, b2, b3);
            }
        }

        float* SsH = Ss + kh * 64 * BSS;
        #pragma unroll
        for (int nt = 0; nt < 4; nt++) {
            int row = m0 + rA;
            int col = nt * 8 + 2 * cA;
            *(float2*)(SsH + row * BSS + col)       = make_float2(sacc[nt][0], sacc[nt][1]);
            *(float2*)(SsH + (row + 8) * BSS + col) = make_float2(sacc[nt][2], sacc[nt][3]);
        }
    }
    __syncthreads();

    // softmax over each src's 16 neighbors; coalesced write to g_ewS (l-major)
    const float skip = attn_skip_p[0];
    const int g  = j >> 4;
    const int jj = j & 15;

    #pragma unroll
    for (int it = 0; it < 4; it++) {
        const int v  = it * 16 + w * 2 + g;
        const int dst = Sd[v * 16 + jj];
        const int col = (dst - (v & ~15) - 1) & 63;        // in [0,32)
        float sc = (Ss[v * BSS + col] + Ss[64 * BSS + v * BSS + col]) * 0.0625f;
        float m = sc;
        #pragma unroll
        for (int off = 8; off > 0; off >>= 1) m = fmaxf(m, __shfl_xor_sync(~0u, m, off));
        float e = __expf(sc - m);
        float Zt = e;
        #pragma unroll
        for (int off = 8; off > 0; off >>= 1) Zt += __shfl_xor_sync(~0u, Zt, off);
        const int eIdx = v * 16 + jj;
        g_ewS[(size_t)bx * 1024 + eIdx] =
            skip * Sew[eIdx] + (1.0f - skip) * e / Zt;
    }
}

// ---------------- K3: transpose ewS (l-major) -> out (e-major) ----------------
__global__ __launch_bounds__(256) void ewT_kernel(float* __restrict__ out)
{
    __shared__ float tile[32][33];
    const int b = blockIdx.z;
    const int l0 = blockIdx.x * 32, e0 = blockIdx.y * 32;
    const int x = threadIdx.x, y = threadIdx.y;
    #pragma unroll
    for (int i = y; i < 32; i += 8)
        tile[i][x] = g_ewS[((size_t)(b * 1024 + l0 + i)) * 1024 + e0 + x];
    __syncthreads();
    float* outEw = out + (size_t)2 * Bx * Ex * Lx;
    #pragma unroll
    for (int i = y; i < 32; i += 8)
        outEw[((size_t)(b * 1024 + e0 + i)) * 1024 + l0 + x] = tile[x][i];
}

extern "C" void kernel_launch(void* const* d_in, const int* in_sizes, int n_in,
                              void* d_out, int out_size)
{
    const float* hs = (const float*)d_in[0];
    const int*   ei = (const int*)  d_in[1];
    const float* ew = (const float*)d_in[2];
    const float* Wq = (const float*)d_in[3];
    const float* bq = (const float*)d_in[4];
    const float* Wk = (const float*)d_in[5];
    const float* bk = (const float*)d_in[6];
    const float* sk = (const float*)d_in[7];
    float* out = (float*)d_out;
    (void)bk;

    pre_a<<<dim3(256, 4), 256>>>(Wq, bq, Wk);
    pre_b<<<256, 256>>>();

    const int smem1 = 128 * F32STR * 4 + 2 * 128 * ASTRh * 2 + 128 * BSTRh * 2
                    + 128 * 4 + 16;
    cudaFuncSetAttribute(gemm1_kernel, cudaFuncAttributeMaxDynamicSharedMemorySize, smem1);
    gemm1_kernel<<<dim3(2048, 2), 256, smem1>>>(hs);

    const int smem2 = 64 * HSTR * 2 * 2 + 2 * 64 * BSS * 4 + 1024 * 4 * 2 + 16;
    cudaFuncSetAttribute(attn_kernel, cudaFuncAttributeMaxDynamicSharedMemorySize, smem2);
    attn_kernel<<<Bx * Lx, 256, smem2>>>(ei, ew, sk, out);

    ewT_kernel<<<dim3(32, 32, Bx), dim3(32, 8)>>>(out);
}

// round 13
// speedup vs baseline: 1.1747x; 1.0060x over previous
#include <cuda_runtime.h>
#include <cuda_fp16.h>
#include <cstdint>
#include <cstddef>

#define Bx 4
#define Vx 64
#define Ex 1024
#define Lx 1024
#define NR (Bx * Vx * Lx)          // 262144 rows

#define ASTRh  40                  // gemm1 fp16 A row stride (halfs)
#define BSTRh  264                 // gemm1 B row stride (halfs)
#define XZSTR  520                 // attn XZ row stride (halfs); 1040B % 128 = 16 -> LDSM ok
#define BSS    36                  // attn score row stride (floats)

__device__ __align__(16) __half g_Mh[256 * 256];      // Mh[n][k] = (Wq^T Wk)[k][n]
__device__ __align__(16) float  g_r[256];             // r[n] = sum_c bq[c]*Wk[c][n]
__device__ __align__(16) float  g_Mp[4 * 256 * 256];  // precompute partials [dq][n][k]
__device__ __align__(16) float  g_rp[4 * 256];        // r partials [dq][n]
__device__ __align__(16) __half g_XZ[(size_t)NR * 512];   // row: [Xh(256) | Z+r (256)]
__device__ __align__(16) float  g_ewS[(size_t)Bx * Lx * Ex]; // ew, l-major staging

__device__ __forceinline__ unsigned packh2(float a, float b) {
    __half2 h = __floats2half2_rn(a, b);
    return *reinterpret_cast<unsigned*>(&h);
}

__device__ __forceinline__ void mma_f16(float (&d)[4], const unsigned (&a)[4],
                                        unsigned b0, unsigned b1) {
    asm volatile("mma.sync.aligned.m16n8k16.row.col.f32.f16.f16.f32 "
                 "{%0,%1,%2,%3}, {%4,%5,%6,%7}, {%8,%9}, {%0,%1,%2,%3};"
                 : "+f"(d[0]), "+f"(d[1]), "+f"(d[2]), "+f"(d[3])
                 : "r"(a[0]), "r"(a[1]), "r"(a[2]), "r"(a[3]), "r"(b0), "r"(b1));
}

__device__ __forceinline__ void ldsm_x4(unsigned &r0, unsigned &r1, unsigned &r2,
                                        unsigned &r3, const void* p) {
    unsigned a = (unsigned)__cvta_generic_to_shared(p);
    asm volatile("ldmatrix.sync.aligned.m8n8.x4.shared.b16 {%0,%1,%2,%3}, [%4];"
                 : "=r"(r0), "=r"(r1), "=r"(r2), "=r"(r3) : "r"(a));
}

__device__ __forceinline__ uint32_t smem_u32(const void* p) {
    return (uint32_t)__cvta_generic_to_shared(p);
}
__device__ __forceinline__ void mbar_init(uint32_t a, unsigned cnt) {
    asm volatile("mbarrier.init.shared.b64 [%0], %1;" :: "r"(a), "r"(cnt) : "memory");
}
__device__ __forceinline__ void mbar_expect_tx(uint32_t a, unsigned bytes) {
    asm volatile("mbarrier.arrive.expect_tx.shared.b64 _, [%0], %1;"
                 :: "r"(a), "r"(bytes) : "memory");
}
__device__ __forceinline__ void fence_proxy_async_sc() {
    asm volatile("fence.proxy.async.shared::cta;" ::: "memory");
}
__device__ __forceinline__ void bulk_g2s(uint32_t dst, const void* src,
                                         unsigned bytes, uint32_t mbar) {
    asm volatile("cp.async.bulk.shared::cta.global.mbarrier::complete_tx::bytes "
                 "[%0], [%1], %2, [%3];"
                 :: "r"(dst), "l"(src), "r"(bytes), "r"(mbar) : "memory");
}
__device__ __forceinline__ void mbar_wait(uint32_t a, unsigned parity) {
    asm volatile(
        "{\n\t.reg .pred P;\n\t"
        "WAITL_%=:\n\t"
        "mbarrier.try_wait.parity.acquire.cta.shared::cta.b64 P, [%0], %1, 0x989680;\n\t"
        "@P bra.uni WAITD_%=;\n\t"
        "bra.uni WAITL_%=;\n\t"
        "WAITD_%=:\n\t}"
        :: "r"(a), "r"(parity) : "memory");
}

// ---------------- K0a: partial M over d-quarters ----------------
__global__ void pre_a(const float* __restrict__ Wq, const float* __restrict__ bq,
                      const float* __restrict__ Wk)
{
    __shared__ float sWk[64];
    __shared__ float red[2];
    const int n = blockIdx.x, dq = blockIdx.y, j = threadIdx.x;
    if (j < 64) sWk[j] = Wk[(dq * 64 + j) * 256 + n];
    __syncthreads();
    float acc = 0.f;
    const float* wq = Wq + (dq * 64) * 256 + j;
    #pragma unroll 8
    for (int dd = 0; dd < 64; dd++)
        acc = fmaf(wq[dd * 256], sWk[dd], acc);
    g_Mp[(dq * 256 + n) * 256 + j] = acc;

    if (j < 64) {
        float pr = bq[dq * 64 + j] * sWk[j];
        #pragma unroll
        for (int off = 16; off > 0; off >>= 1)
            pr += __shfl_xor_sync(~0u, pr, off);
        if ((j & 31) == 0) red[j >> 5] = pr;
    }
    __syncthreads();
    if (j == 0) g_rp[dq * 256 + n] = red[0] + red[1];
}

// ---------------- K0b: sum partials -> fp16 M, r ----------------
__global__ void pre_b()
{
    const int n = blockIdx.x, j = threadIdx.x;
    float s = g_Mp[n * 256 + j] + g_Mp[(256 + n) * 256 + j]
            + g_Mp[(512 + n) * 256 + j] + g_Mp[(768 + n) * 256 + j];
    g_Mh[n * 256 + j] = __float2half_rn(s);
    if (j == 0)
        g_r[n] = g_rp[n] + g_rp[256 + n] + g_rp[512 + n] + g_rp[768 + n];
}

// ---------------- K1: fused convert + GEMM  Z = Xh @ Mh^T + r ----------------
// grid (2048, 2): 128-row tile x 128-n half. 256 threads = 4m x 2n warps.
// A path: hs --LDG(fp32,regs)--> cvt --STS--> Ah (no fp32 smem stage).
__global__ __launch_bounds__(256, 2) void gemm1_kernel(const float* __restrict__ hs)
{
    extern __shared__ char smraw1[];
    __half* Ah  = (__half*)smraw1;                       // 2 x 128 x ASTRh
    __half* Bs  = Ah + 2 * 128 * ASTRh;                  // 128 x BSTRh
    float*  Sr  = (float*)(Bs + 128 * BSTRh);            // 128
    unsigned long long* mb = (unsigned long long*)(Sr + 128);
    __half* Zst = Bs;                                    // epilogue overlay

    const int t = threadIdx.x, w = t >> 5, j = t & 31;
    const int r0 = blockIdx.x * 128;
    const int n0 = blockIdx.y * 128;
    const int rA = j >> 2, cA = j & 3;
    const int mb_ = (w & 3) * 32, nb = (w >> 2) * 64;
    const uint32_t mba = smem_u32(mb);

    if (t == 0) {
        mbar_init(mba, 1);
        fence_proxy_async_sc();
        mbar_expect_tx(mba, 128 * 512);
    }
    __syncthreads();
    // stage B via bulk copies (128 rows x 512B)
    if (t < 128)
        bulk_g2s(smem_u32(Bs + t * BSTRh), g_Mh + (n0 + t) * 256, 512, mba);
    if (t < 32) ((float4*)Sr)[t] = __ldg((const float4*)(g_r + n0) + t);

    // A convert mapping: 2 threads per row, 16 floats each
    const int cvrow = t >> 1, cvh = t & 1;
    const float* hp = hs + (size_t)(r0 + cvrow) * 256 + cvh * 16;
    __half* gx = g_XZ + (size_t)(r0 + cvrow) * 512 + cvh * 16;

    float4 nxt0, nxt1, nxt2, nxt3;
    uint4 co0, co1;
    // prologue: load + convert chunk 0
    nxt0 = *(const float4*)(hp);
    nxt1 = *(const float4*)(hp + 4);
    nxt2 = *(const float4*)(hp + 8);
    nxt3 = *(const float4*)(hp + 12);
    co0.x = packh2(nxt0.x, nxt0.y); co0.y = packh2(nxt0.z, nxt0.w);
    co0.z = packh2(nxt1.x, nxt1.y); co0.w = packh2(nxt1.z, nxt1.w);
    co1.x = packh2(nxt2.x, nxt2.y); co1.y = packh2(nxt2.z, nxt2.w);
    co1.z = packh2(nxt3.x, nxt3.y); co1.w = packh2(nxt3.z, nxt3.w);

    float acc[2][8][4];
    #pragma unroll
    for (int a = 0; a < 2; a++)
        #pragma unroll
        for (int c = 0; c < 8; c++)
            #pragma unroll
            for (int q = 0; q < 4; q++) acc[a][c][q] = 0.f;

    mbar_wait(mba, 0);           // B resident

    #pragma unroll 1
    for (int kt = 0; kt < 8; kt++) {
        // store current converted chunk to Ah + g_XZ (n-half 0 only)
        __half* A = Ah + (kt & 1) * 128 * ASTRh;
        {
            __half* ap = A + cvrow * ASTRh + cvh * 16;
            *(uint4*)(ap) = co0;
            *(uint4*)(ap + 8) = co1;
            if (blockIdx.y == 0) {
                *(uint4*)(gx + kt * 32) = co0;
                *(uint4*)(gx + kt * 32 + 8) = co1;
            }
        }
        // issue LDGs for next chunk (overlap with barrier + mma)
        if (kt < 7) {
            const float* np = hp + (kt + 1) * 32;
            nxt0 = *(const float4*)(np);
            nxt1 = *(const float4*)(np + 4);
            nxt2 = *(const float4*)(np + 8);
            nxt3 = *(const float4*)(np + 12);
        }
        __syncthreads();

        #pragma unroll
        for (int ks = 0; ks < 2; ks++) {
            const int kcB = kt * 32 + ks * 16;
            unsigned a[2][4];
            #pragma unroll
            for (int mt = 0; mt < 2; mt++) {
                int arow = mb_ + mt * 16 + (j & 7) + ((j >> 3) & 1) * 8;
                ldsm_x4(a[mt][0], a[mt][1], a[mt][2], a[mt][3],
                        A + arow * ASTRh + ks * 16 + (j >> 4) * 8);
            }
            #pragma unroll
            for (int p = 0; p < 4; p++) {
                unsigned b0, b1, b2, b3;
                int brow = nb + p * 16 + (j >> 4) * 8 + (j & 7);
                ldsm_x4(b0, b1, b2, b3,
                        Bs + brow * BSTRh + kcB + ((j >> 3) & 1) * 8);
                mma_f16(acc[0][2 * p],     a[0], b0, b1);
                mma_f16(acc[1][2 * p],     a[1], b0, b1);
                mma_f16(acc[0][2 * p + 1], a[0], b2, b3);
                mma_f16(acc[1][2 * p + 1], a[1], b2, b3);
            }
        }
        // convert the prefetched chunk after mma (LDGs have landed by now)
        if (kt < 7) {
            co0.x = packh2(nxt0.x, nxt0.y); co0.y = packh2(nxt0.z, nxt0.w);
            co0.z = packh2(nxt1.x, nxt1.y); co0.w = packh2(nxt1.z, nxt1.w);
            co1.x = packh2(nxt2.x, nxt2.y); co1.y = packh2(nxt2.z, nxt2.w);
            co1.z = packh2(nxt3.x, nxt3.y); co1.w = packh2(nxt3.z, nxt3.w);
        }
    }
    __syncthreads();   // last mma's ldmatrix reads done before overlaying Bs

    // epilogue: add r, pack fp16 into overlay, coalesced STG
    #pragma unroll
    for (int mt = 0; mt < 2; mt++)
        #pragma unroll
        for (int nt = 0; nt < 8; nt++) {
            int row = mb_ + mt * 16 + rA;
            int col = nb + nt * 8 + 2 * cA;
            float rc0 = Sr[col], rc1 = Sr[col + 1];
            *(unsigned*)(Zst + row * BSTRh + col) =
                packh2(acc[mt][nt][0] + rc0, acc[mt][nt][1] + rc1);
            *(unsigned*)(Zst + (row + 8) * BSTRh + col) =
                packh2(acc[mt][nt][2] + rc0, acc[mt][nt][3] + rc1);
        }
    __syncthreads();
    // Z columns live at [256 + n0, 256 + n0 + 128) of each 512-half g_XZ row
    #pragma unroll
    for (int i = 0; i < 8; i++) {
        int idx = i * 256 + t, row = idx >> 4, q = idx & 15;
        *(uint4*)(g_XZ + (size_t)(r0 + row) * 512 + 256 + n0 + q * 8) =
            *(const uint4*)(Zst + row * BSTRh + q * 8);
    }
}

// ---------------- K2: per (b,l): banded S = (Z+r).X^T, softmax ----------------
__global__ __launch_bounds__(256, 2)
void attn_kernel(const int*   __restrict__ edge_index,
                 const float* __restrict__ edge_weight,
                 const float* __restrict__ attn_skip_p,
                 float* __restrict__ out)
{
    extern __shared__ char smraw[];
    __half* XZ = (__half*)smraw;                       // 64 x XZSTR (X | Z)
    float*  Ss = (float*)(XZ + 64 * XZSTR);            // 2 x 64 x BSS
    int*    Sd = (int*)(Ss + 2 * 64 * BSS);            // 1024
    float*  Sew = (float*)(Sd + 1024);                 // 1024
    unsigned long long* mb = (unsigned long long*)(Sew + 1024);

    const int bx = blockIdx.x;
    const int b = bx >> 10, l = bx & 1023;
    const int t = threadIdx.x, w = t >> 5, j = t & 31;
    const int rA = j >> 2, cA = j & 3;
    const uint32_t mba = smem_u32(mb);

    if (t == 0) {
        mbar_init(mba, 1);
        fence_proxy_async_sc();
        mbar_expect_tx(mba, 64 * 1024);
    }
    __syncthreads();
    // stage X|Z rows: 64 bulk copies of 1KB
    if (t < 64) {
        size_t rowoff = ((size_t)(b * Vx + t) * Lx + l) * 512;
        bulk_g2s(smem_u32(XZ + t * XZSTR), g_XZ + rowoff, 1024, mba);
    }

    // ei output fill (overlaps bulk)
    {
        const int base = bx * 2048;
        #pragma unroll
        for (int r = 0; r < 8; r++) {
            int idx = base + r * 256 + t;
            out[idx] = (float)edge_index[idx >> 10];
        }
    }
    // dst + edge weights
    {
        const int*   dsts = edge_index + Bx * Ex + b * Ex;
        const float* ews  = edge_weight + b * Ex;
        #pragma unroll
        for (int i = 0; i < 4; i++) {
            Sd[i * 256 + t]  = dsts[i * 256 + t];
            Sew[i * 256 + t] = ews[i * 256 + t];
        }
    }
    mbar_wait(mba, 0);
    __syncthreads();

    // banded GEMM: S[64][32] = Z @ X[band]^T
    {
        float sacc[4][4];
        #pragma unroll
        for (int c = 0; c < 4; c++)
            #pragma unroll
            for (int q = 0; q < 4; q++) sacc[c][q] = 0.f;

        const int m0 = (w & 3) * 16;
        const int kh = w >> 2;

        #pragma unroll
        for (int ks = 0; ks < 8; ks++) {
            const int kc = kh * 128 + ks * 16;
            unsigned a[4];
            {
                int arow = m0 + (j & 7) + ((j >> 3) & 1) * 8;
                ldsm_x4(a[0], a[1], a[2], a[3],
                        XZ + arow * XZSTR + 256 + kc + (j >> 4) * 8);   // Z part
            }
            #pragma unroll
            for (int p = 0; p < 2; p++) {
                unsigned b0, b1, b2, b3;
                int nrow = (m0 + 1 + (2 * p + (j >> 4)) * 8 + (j & 7)) & 63;
                ldsm_x4(b0, b1, b2, b3,
                        XZ + nrow * XZSTR + kc + ((j >> 3) & 1) * 8);   // X part
                mma_f16(sacc[2 * p],     a, b0, b1);
                mma_f16(sacc[2 * p + 1], a, b2, b3);
            }
        }

        float* SsH = Ss + kh * 64 * BSS;
        #pragma unroll
        for (int nt = 0; nt < 4; nt++) {
            int row = m0 + rA;
            int col = nt * 8 + 2 * cA;
            *(float2*)(SsH + row * BSS + col)       = make_float2(sacc[nt][0], sacc[nt][1]);
            *(float2*)(SsH + (row + 8) * BSS + col) = make_float2(sacc[nt][2], sacc[nt][3]);
        }
    }
    __syncthreads();

    // softmax over each src's 16 neighbors; coalesced write to g_ewS (l-major)
    const float skip = attn_skip_p[0];
    const int g  = j >> 4;
    const int jj = j & 15;

    #pragma unroll
    for (int it = 0; it < 4; it++) {
        const int v  = it * 16 + w * 2 + g;
        const int dst = Sd[v * 16 + jj];
        const int col = (dst - (v & ~15) - 1) & 63;        // in [0,32)
        float sc = (Ss[v * BSS + col] + Ss[64 * BSS + v * BSS + col]) * 0.0625f;
        float m = sc;
        #pragma unroll
        for (int off = 8; off > 0; off >>= 1) m = fmaxf(m, __shfl_xor_sync(~0u, m, off));
        float e = __expf(sc - m);
        float Zt = e;
        #pragma unroll
        for (int off = 8; off > 0; off >>= 1) Zt += __shfl_xor_sync(~0u, Zt, off);
        const int eIdx = v * 16 + jj;
        g_ewS[(size_t)bx * 1024 + eIdx] =
            skip * Sew[eIdx] + (1.0f - skip) * e / Zt;
    }
}

// ---------------- K3: transpose ewS (l-major) -> out (e-major) ----------------
__global__ __launch_bounds__(256) void ewT_kernel(float* __restrict__ out)
{
    __shared__ float tile[32][33];
    const int b = blockIdx.z;
    const int l0 = blockIdx.x * 32, e0 = blockIdx.y * 32;
    const int x = threadIdx.x, y = threadIdx.y;
    #pragma unroll
    for (int i = y; i < 32; i += 8)
        tile[i][x] = g_ewS[((size_t)(b * 1024 + l0 + i)) * 1024 + e0 + x];
    __syncthreads();
    float* outEw = out + (size_t)2 * Bx * Ex * Lx;
    #pragma unroll
    for (int i = y; i < 32; i += 8)
        outEw[((size_t)(b * 1024 + e0 + i)) * 1024 + l0 + x] = tile[x][i];
}

extern "C" void kernel_launch(void* const* d_in, const int* in_sizes, int n_in,
                              void* d_out, int out_size)
{
    const float* hs = (const float*)d_in[0];
    const int*   ei = (const int*)  d_in[1];
    const float* ew = (const float*)d_in[2];
    const float* Wq = (const float*)d_in[3];
    const float* bq = (const float*)d_in[4];
    const float* Wk = (const float*)d_in[5];
    const float* bk = (const float*)d_in[6];
    const float* sk = (const float*)d_in[7];
    float* out = (float*)d_out;
    (void)bk;

    pre_a<<<dim3(256, 4), 256>>>(Wq, bq, Wk);
    pre_b<<<256, 256>>>();

    const int smem1 = 2 * 128 * ASTRh * 2 + 128 * BSTRh * 2 + 128 * 4 + 16;
    cudaFuncSetAttribute(gemm1_kernel, cudaFuncAttributeMaxDynamicSharedMemorySize, smem1);
    gemm1_kernel<<<dim3(2048, 2), 256, smem1>>>(hs);

    const int smem2 = 64 * XZSTR * 2 + 2 * 64 * BSS * 4 + 1024 * 4 * 2 + 16;
    cudaFuncSetAttribute(attn_kernel, cudaFuncAttributeMaxDynamicSharedMemorySize, smem2);
    attn_kernel<<<Bx * Lx, 256, smem2>>>(ei, ew, sk, out);

    ewT_kernel<<<dim3(32, 32, Bx), dim3(32, 8)>>>(out);
}